// round 11
// baseline (speedup 1.0000x reference)
#include <cuda_runtime.h>
#include <cub/cub.cuh>
#include <stdint.h>

#define BB   256
#define NN   65536
#define KK   52428
#define NTOT (BB * NN)

// ---------------- static device scratch (no allocs allowed) ----------------
__device__ unsigned long long g_k1a[NTOT];
__device__ unsigned long long g_k1b[NTOT];
__device__ unsigned long long g_k2a[NTOT];
__device__ unsigned long long g_k2b[NTOT];
__device__ unsigned char      g_temp[64u * 1024u * 1024u];
__device__ float              g_sel1[(size_t)BB * KK * 3];
__device__ float              g_sel2[(size_t)BB * KK * 3];
__device__ float              g_cpt[2][BB][3];   // crop-center points
__device__ unsigned           g_bmin[2][BB][3];  // encoded float atomics
__device__ unsigned           g_bmax[2][BB][3];
__device__ unsigned           g_rad[2][BB];      // max d^2 bits (nonneg float)
__device__ float              g_bc[2][BB][3];    // bbox centers
__device__ float              g_invr[2][BB];
__device__ float              g_cs[2][BB][2];    // cos, sin
__device__ float              g_theta[2][BB];

// ---------------- JAX threefry2x32 (exact) ----------------
__device__ __forceinline__ void tf2x32(unsigned k0, unsigned k1,
                                       unsigned c0, unsigned c1,
                                       unsigned& o0, unsigned& o1) {
    unsigned ks0 = k0, ks1 = k1, ks2 = k0 ^ k1 ^ 0x1BD11BDAu;
    unsigned x0 = c0 + ks0, x1 = c1 + ks1;
#define TF_RND(r) { x0 += x1; x1 = (x1 << (r)) | (x1 >> (32 - (r))); x1 ^= x0; }
    TF_RND(13) TF_RND(15) TF_RND(26) TF_RND(6)
    x0 += ks1; x1 += ks2 + 1u;
    TF_RND(17) TF_RND(29) TF_RND(16) TF_RND(24)
    x0 += ks2; x1 += ks0 + 2u;
    TF_RND(13) TF_RND(15) TF_RND(26) TF_RND(6)
    x0 += ks0; x1 += ks1 + 3u;
    TF_RND(17) TF_RND(29) TF_RND(16) TF_RND(24)
    x0 += ks1; x1 += ks2 + 4u;
    TF_RND(13) TF_RND(15) TF_RND(26) TF_RND(6)
    x0 += ks2; x1 += ks0 + 5u;
#undef TF_RND
    o0 = x0; o1 = x1;
}

__device__ __forceinline__ float bits_to_theta(unsigned u) {
    // jax.random.uniform: bitcast((bits>>9)|0x3f800000) - 1, times f32(2*pi), max(0,.)
    float f = __uint_as_float((u >> 9) | 0x3F800000u) - 1.0f;
    return fmaxf(0.0f, f * 6.2831855f);
}

// monotone float<->uint encodings for min/max atomics
__device__ __forceinline__ unsigned fenc(float f) {
    unsigned u = __float_as_uint(f);
    return (u & 0x80000000u) ? ~u : (u | 0x80000000u);
}
__device__ __forceinline__ float fdec(unsigned u) {
    return __uint_as_float((u & 0x80000000u) ? (u ^ 0x80000000u) : ~u);
}

// ---------------- kernels ----------------
__global__ void init_kernel(const float* __restrict__ pts,
                            const int* __restrict__ ci1,
                            const int* __restrict__ ci2) {
    int t = threadIdx.x;  // 256 threads, one block
    for (int v = 0; v < 2; v++) {
        for (int c = 0; c < 3; c++) { g_bmin[v][t][c] = 0xFFFFFFFFu; g_bmax[v][t][c] = 0u; }
        g_rad[v][t] = 0u;
    }
    int i1 = ci1[t], i2 = ci2[t];
    const float* p1 = pts + ((size_t)t * NN + (unsigned)i1) * 3;
    const float* p2 = pts + ((size_t)t * NN + (unsigned)i2) * 3;
    for (int c = 0; c < 3; c++) { g_cpt[0][t][c] = p1[c]; g_cpt[1][t][c] = p2[c]; }

    // ---- JAX partitionable threefry (default since jax 0.4.30) ----
    // split(key(42), 2): new key i = both output words of tf2x32(key, (0, i))
    unsigned k1a_, k1b_, k2a_, k2b_;
    tf2x32(0u, 42u, 0u, 0u, k1a_, k1b_);   // rk1
    tf2x32(0u, 42u, 0u, 1u, k2a_, k2b_);   // rk2
    // random_bits(rk, 32, (256,)): element i = b1 ^ b2 of tf2x32(rk, (0, i))
    unsigned o0, o1;
    tf2x32(k1a_, k1b_, 0u, (unsigned)t, o0, o1);
    g_theta[0][t] = bits_to_theta(o0 ^ o1);
    tf2x32(k2a_, k2b_, 0u, (unsigned)t, o0, o1);
    g_theta[1][t] = bits_to_theta(o0 ^ o1);
}

__global__ void keys_kernel(const float* __restrict__ pts) {
    int gid = blockIdx.x * 256 + threadIdx.x;
    int b = gid >> 16;
    unsigned i = (unsigned)gid & 0xFFFFu;
    size_t base = (size_t)gid * 3;
    float x = pts[base], y = pts[base + 1], z = pts[base + 2];
#pragma unroll
    for (int v = 0; v < 2; v++) {
        float dx = __fsub_rn(x, g_cpt[v][b][0]);
        float dy = __fsub_rn(y, g_cpt[v][b][1]);
        float dz = __fsub_rn(z, g_cpt[v][b][2]);
        float sx = __fmul_rn(dx, dx);
        float sy = __fmul_rn(dy, dy);
        float sz = __fmul_rn(dz, dz);
        // Candidate F on BOTH views: (sx + sz) + sy — the LLVM/SIMD
        // horizontal-reduce association for [sx,sy,sz,0]:
        //   [sx,sy] + [sz,0] = [sx+sz, sy] ; lanes folded -> (sx+sz)+sy.
        // Evidence: plain-add assocs f1/C tie at the 0.0345 floor, fma f2 is
        // worse -> truth is the remaining plain-add association, i.e. F.
        float d2 = __fadd_rn(__fadd_rn(sx, sz), sy);
        unsigned long long key = ((unsigned long long)b << 48) |
                                 ((unsigned long long)__float_as_uint(d2) << 16) | i;
        if (v == 0) g_k1a[gid] = key; else g_k2a[gid] = key;  // lowest-index ties (confirmed)
    }
}

__global__ void gather_kernel(const unsigned long long* __restrict__ sorted,
                              const float* __restrict__ pts,
                              float* __restrict__ sel, int view) {
    int b = blockIdx.y;
    int j = blockIdx.x * 256 + threadIdx.x;
    const float INF = __int_as_float(0x7f800000);
    float mnx = INF, mny = INF, mnz = INF, mxx = -INF, mxy = -INF, mxz = -INF;
    if (j < KK) {
        unsigned long long key = sorted[((size_t)b << 16) + (unsigned)j];
        unsigned idx = (unsigned)(key & 0xFFFFull);
        const float* p = pts + (((size_t)b << 16) + idx) * 3;
        float x = p[0], y = p[1], z = p[2];
        size_t o = ((size_t)b * KK + (unsigned)j) * 3;
        sel[o] = x; sel[o + 1] = y; sel[o + 2] = z;
        mnx = mxx = x; mny = mxy = y; mnz = mxz = z;
    }
#pragma unroll
    for (int off = 16; off; off >>= 1) {
        mnx = fminf(mnx, __shfl_xor_sync(0xFFFFFFFFu, mnx, off));
        mny = fminf(mny, __shfl_xor_sync(0xFFFFFFFFu, mny, off));
        mnz = fminf(mnz, __shfl_xor_sync(0xFFFFFFFFu, mnz, off));
        mxx = fmaxf(mxx, __shfl_xor_sync(0xFFFFFFFFu, mxx, off));
        mxy = fmaxf(mxy, __shfl_xor_sync(0xFFFFFFFFu, mxy, off));
        mxz = fmaxf(mxz, __shfl_xor_sync(0xFFFFFFFFu, mxz, off));
    }
    __shared__ float smn[8][3], smx[8][3];
    int w = threadIdx.x >> 5, l = threadIdx.x & 31;
    if (l == 0) {
        smn[w][0] = mnx; smn[w][1] = mny; smn[w][2] = mnz;
        smx[w][0] = mxx; smx[w][1] = mxy; smx[w][2] = mxz;
    }
    __syncthreads();
    if (threadIdx.x == 0) {
        float a[3], c[3];
        for (int d = 0; d < 3; d++) { a[d] = smn[0][d]; c[d] = smx[0][d]; }
        for (int ww = 1; ww < 8; ww++)
            for (int d = 0; d < 3; d++) {
                a[d] = fminf(a[d], smn[ww][d]);
                c[d] = fmaxf(c[d], smx[ww][d]);
            }
        for (int d = 0; d < 3; d++) {
            atomicMin(&g_bmin[view][b][d], fenc(a[d]));
            atomicMax(&g_bmax[view][b][d], fenc(c[d]));
        }
    }
}

__global__ void finalize_bbox_kernel() {
    int t = blockIdx.x * 256 + threadIdx.x;  // 512
    int v = t >> 8, b = t & 255;
    for (int c = 0; c < 3; c++)
        g_bc[v][b][c] = (fdec(g_bmin[v][b][c]) + fdec(g_bmax[v][b][c])) * 0.5f;
}

__global__ void radius_kernel(const float* __restrict__ sel, int view) {
    int b = blockIdx.y;
    int j = blockIdx.x * 256 + threadIdx.x;
    float d2 = 0.0f;
    if (j < KK) {
        size_t o = ((size_t)b * KK + (unsigned)j) * 3;
        float dx = sel[o] - g_bc[view][b][0];
        float dy = sel[o + 1] - g_bc[view][b][1];
        float dz = sel[o + 2] - g_bc[view][b][2];
        d2 = dx * dx + dy * dy + dz * dz;
    }
#pragma unroll
    for (int off = 16; off; off >>= 1)
        d2 = fmaxf(d2, __shfl_xor_sync(0xFFFFFFFFu, d2, off));
    __shared__ float sm[8];
    int w = threadIdx.x >> 5, l = threadIdx.x & 31;
    if (l == 0) sm[w] = d2;
    __syncthreads();
    if (threadIdx.x == 0) {
        float m = sm[0];
        for (int ww = 1; ww < 8; ww++) m = fmaxf(m, sm[ww]);
        atomicMax(&g_rad[view][b], __float_as_uint(m));  // nonneg: bits monotone
    }
}

__global__ void finalize_r_kernel(float* __restrict__ out) {
    int t = blockIdx.x * 256 + threadIdx.x;  // 512
    int v = t >> 8, b = t & 255;
    float r = sqrtf(__uint_as_float(g_rad[v][b]));  // sqrt(max d2) == max(sqrt d2)
    g_invr[v][b] = 1.0f / r;
    float s, c;
    sincosf(g_theta[v][b], &s, &c);
    g_cs[v][b][0] = c; g_cs[v][b][1] = s;
    if (v == 0)
        for (int d = 0; d < 3; d++)
            out[b * 3 + d] = g_bc[1][b][d] - g_bc[0][b][d];  // relative_center = c2 - c1
}

__global__ void write_kernel(const float* __restrict__ sel, float* __restrict__ out,
                             int view) {
    int b = blockIdx.y;
    int j = blockIdx.x * 256 + threadIdx.x;
    if (j >= KK) return;
    size_t o = ((size_t)b * KK + (unsigned)j) * 3;
    float inv = g_invr[view][b];
    float px = (sel[o]     - g_bc[view][b][0]) * inv;
    float py = (sel[o + 1] - g_bc[view][b][1]) * inv;
    float pz = (sel[o + 2] - g_bc[view][b][2]) * inv;
    float c = g_cs[view][b][0], s = g_cs[view][b][1];
    float ox = px * c + py * s;   // einsum with R = [[c,-s,0],[s,c,0],[0,0,1]]
    float oy = py * c - px * s;
    size_t base = 768 + (size_t)view * ((size_t)BB * KK * 3);
    out[base + o]     = ox;
    out[base + o + 1] = oy;
    out[base + o + 2] = pz;
}

// ---------------- host ----------------
extern "C" void kernel_launch(void* const* d_in, const int* in_sizes, int n_in,
                              void* d_out, int out_size) {
    const float* pts = (const float*)d_in[0];
    const int* ci1 = (const int*)d_in[1];
    const int* ci2 = (const int*)d_in[2];
    float* out = (float*)d_out;

    unsigned long long *k1a, *k1b, *k2a, *k2b;
    void *tmp; float *sel1, *sel2;
    cudaGetSymbolAddress((void**)&k1a, g_k1a);
    cudaGetSymbolAddress((void**)&k1b, g_k1b);
    cudaGetSymbolAddress((void**)&k2a, g_k2a);
    cudaGetSymbolAddress((void**)&k2b, g_k2b);
    cudaGetSymbolAddress(&tmp, g_temp);
    cudaGetSymbolAddress((void**)&sel1, g_sel1);
    cudaGetSymbolAddress((void**)&sel2, g_sel2);

    init_kernel<<<1, 256>>>(pts, ci1, ci2);
    keys_kernel<<<NTOT / 256, 256>>>(pts);

    // Stable sort over bits [16,56): (batch | d2bits); ties lowest-index-first.
    cub::DoubleBuffer<unsigned long long> db1(k1a, k1b);
    size_t tb = sizeof(g_temp);
    cub::DeviceRadixSort::SortKeys(tmp, tb, db1, NTOT, 16, 56);
    const unsigned long long* s1 = db1.Current();

    cub::DoubleBuffer<unsigned long long> db2(k2a, k2b);
    tb = sizeof(g_temp);
    cub::DeviceRadixSort::SortKeys(tmp, tb, db2, NTOT, 16, 56);
    const unsigned long long* s2 = db2.Current();

    dim3 grid((KK + 255) / 256, BB);
    gather_kernel<<<grid, 256>>>(s1, pts, sel1, 0);
    gather_kernel<<<grid, 256>>>(s2, pts, sel2, 1);
    finalize_bbox_kernel<<<2, 256>>>();
    radius_kernel<<<grid, 256>>>(sel1, 0);
    radius_kernel<<<grid, 256>>>(sel2, 1);
    finalize_r_kernel<<<2, 256>>>(out);
    write_kernel<<<grid, 256>>>(sel1, out, 0);
    write_kernel<<<grid, 256>>>(sel2, out, 1);
}

// round 14
// speedup vs baseline: 1.1444x; 1.1444x over previous
#include <cuda_runtime.h>
#include <cub/cub.cuh>
#include <stdint.h>

#define BB   256
#define NN   65536
#define KK   52428
#define NTOT (BB * NN)

// ---------------- static device scratch (no allocs allowed) ----------------
__device__ unsigned g_d2_1[NTOT];   // view1 d2 keys (input)
__device__ unsigned g_d2_2[NTOT];   // view2 d2 keys (input)
__device__ unsigned g_d2alt[NTOT];  // shared alternate key buffer
__device__ unsigned g_v1a[NTOT];    // view1 payload dbuf
__device__ unsigned g_v1b[NTOT];
__device__ unsigned g_v2a[NTOT];    // view2 payload dbuf
__device__ unsigned g_v2b[NTOT];
__device__ unsigned char g_temp[64u * 1024u * 1024u];
__device__ float    g_sel1[(size_t)BB * KK * 3];
__device__ float    g_sel2[(size_t)BB * KK * 3];
__device__ float    g_cpt[2][BB][3];   // crop-center points
__device__ unsigned g_bmin[2][BB][3];  // encoded float atomics
__device__ unsigned g_bmax[2][BB][3];
__device__ unsigned g_rad[2][BB];      // max d^2 bits (nonneg float)
__device__ float    g_bc[2][BB][3];    // bbox centers
__device__ float    g_invr[2][BB];
__device__ float    g_cs[2][BB][2];    // cos, sin
__device__ float    g_theta[2][BB];

// ---------------- JAX threefry2x32 (exact) ----------------
__device__ __forceinline__ void tf2x32(unsigned k0, unsigned k1,
                                       unsigned c0, unsigned c1,
                                       unsigned& o0, unsigned& o1) {
    unsigned ks0 = k0, ks1 = k1, ks2 = k0 ^ k1 ^ 0x1BD11BDAu;
    unsigned x0 = c0 + ks0, x1 = c1 + ks1;
#define TF_RND(r) { x0 += x1; x1 = (x1 << (r)) | (x1 >> (32 - (r))); x1 ^= x0; }
    TF_RND(13) TF_RND(15) TF_RND(26) TF_RND(6)
    x0 += ks1; x1 += ks2 + 1u;
    TF_RND(17) TF_RND(29) TF_RND(16) TF_RND(24)
    x0 += ks2; x1 += ks0 + 2u;
    TF_RND(13) TF_RND(15) TF_RND(26) TF_RND(6)
    x0 += ks0; x1 += ks1 + 3u;
    TF_RND(17) TF_RND(29) TF_RND(16) TF_RND(24)
    x0 += ks1; x1 += ks2 + 4u;
    TF_RND(13) TF_RND(15) TF_RND(26) TF_RND(6)
    x0 += ks2; x1 += ks0 + 5u;
#undef TF_RND
    o0 = x0; o1 = x1;
}

__device__ __forceinline__ float bits_to_theta(unsigned u) {
    float f = __uint_as_float((u >> 9) | 0x3F800000u) - 1.0f;
    return fmaxf(0.0f, f * 6.2831855f);
}

// monotone float<->uint encodings for min/max atomics
__device__ __forceinline__ unsigned fenc(float f) {
    unsigned u = __float_as_uint(f);
    return (u & 0x80000000u) ? ~u : (u | 0x80000000u);
}
__device__ __forceinline__ float fdec(unsigned u) {
    return __uint_as_float((u & 0x80000000u) ? (u ^ 0x80000000u) : ~u);
}

// ---------------- kernels ----------------
__global__ void init_kernel(const float* __restrict__ pts,
                            const int* __restrict__ ci1,
                            const int* __restrict__ ci2) {
    int t = threadIdx.x;  // 256 threads, one block
    for (int v = 0; v < 2; v++) {
        for (int c = 0; c < 3; c++) { g_bmin[v][t][c] = 0xFFFFFFFFu; g_bmax[v][t][c] = 0u; }
        g_rad[v][t] = 0u;
    }
    int i1 = ci1[t], i2 = ci2[t];
    const float* p1 = pts + ((size_t)t * NN + (unsigned)i1) * 3;
    const float* p2 = pts + ((size_t)t * NN + (unsigned)i2) * 3;
    for (int c = 0; c < 3; c++) { g_cpt[0][t][c] = p1[c]; g_cpt[1][t][c] = p2[c]; }

    // JAX partitionable threefry (confirmed): split -> tf(key,(0,i)); bits = o0^o1
    unsigned k1a_, k1b_, k2a_, k2b_;
    tf2x32(0u, 42u, 0u, 0u, k1a_, k1b_);   // rk1
    tf2x32(0u, 42u, 0u, 1u, k2a_, k2b_);   // rk2
    unsigned o0, o1;
    tf2x32(k1a_, k1b_, 0u, (unsigned)t, o0, o1);
    g_theta[0][t] = bits_to_theta(o0 ^ o1);
    tf2x32(k2a_, k2b_, 0u, (unsigned)t, o0, o1);
    g_theta[1][t] = bits_to_theta(o0 ^ o1);
}

__global__ void keys_kernel(const float* __restrict__ pts) {
    int gid = blockIdx.x * 256 + threadIdx.x;
    int b = gid >> 16;
    size_t base = (size_t)gid * 3;
    float x = pts[base], y = pts[base + 1], z = pts[base + 2];
#pragma unroll
    for (int v = 0; v < 2; v++) {
        float dx = __fsub_rn(x, g_cpt[v][b][0]);
        float dy = __fsub_rn(y, g_cpt[v][b][1]);
        float dz = __fsub_rn(z, g_cpt[v][b][2]);
        float sx = __fmul_rn(dx, dx);
        float sy = __fmul_rn(dy, dy);
        float sz = __fmul_rn(dz, dz);
        // CONFIRMED formula F: (sx + sz) + sy — bit-exact vs reference.
        float d2 = __fadd_rn(__fadd_rn(sx, sz), sy);
        if (v == 0) g_d2_1[gid] = __float_as_uint(d2);
        else        g_d2_2[gid] = __float_as_uint(d2);
    }
    // Payload iota: gid == (batch<<16)|idx. Same input for both views' dbufs.
    g_v1a[gid] = (unsigned)gid;
    g_v2a[gid] = (unsigned)gid;
}

__global__ void gather_kernel(const unsigned* __restrict__ sorted,
                              const float* __restrict__ pts,
                              float* __restrict__ sel, int view) {
    int b = blockIdx.y;
    int j = blockIdx.x * 256 + threadIdx.x;
    const float INF = __int_as_float(0x7f800000);
    float mnx = INF, mny = INF, mnz = INF, mxx = -INF, mxy = -INF, mxz = -INF;
    if (j < KK) {
        unsigned idx = sorted[((size_t)b << 16) + (unsigned)j] & 0xFFFFu;
        const float* p = pts + (((size_t)b << 16) + idx) * 3;
        float x = p[0], y = p[1], z = p[2];
        size_t o = ((size_t)b * KK + (unsigned)j) * 3;
        sel[o] = x; sel[o + 1] = y; sel[o + 2] = z;
        mnx = mxx = x; mny = mxy = y; mnz = mxz = z;
    }
#pragma unroll
    for (int off = 16; off; off >>= 1) {
        mnx = fminf(mnx, __shfl_xor_sync(0xFFFFFFFFu, mnx, off));
        mny = fminf(mny, __shfl_xor_sync(0xFFFFFFFFu, mny, off));
        mnz = fminf(mnz, __shfl_xor_sync(0xFFFFFFFFu, mnz, off));
        mxx = fmaxf(mxx, __shfl_xor_sync(0xFFFFFFFFu, mxx, off));
        mxy = fmaxf(mxy, __shfl_xor_sync(0xFFFFFFFFu, mxy, off));
        mxz = fmaxf(mxz, __shfl_xor_sync(0xFFFFFFFFu, mxz, off));
    }
    __shared__ float smn[8][3], smx[8][3];
    int w = threadIdx.x >> 5, l = threadIdx.x & 31;
    if (l == 0) {
        smn[w][0] = mnx; smn[w][1] = mny; smn[w][2] = mnz;
        smx[w][0] = mxx; smx[w][1] = mxy; smx[w][2] = mxz;
    }
    __syncthreads();
    if (threadIdx.x == 0) {
        float a[3], c[3];
        for (int d = 0; d < 3; d++) { a[d] = smn[0][d]; c[d] = smx[0][d]; }
        for (int ww = 1; ww < 8; ww++)
            for (int d = 0; d < 3; d++) {
                a[d] = fminf(a[d], smn[ww][d]);
                c[d] = fmaxf(c[d], smx[ww][d]);
            }
        for (int d = 0; d < 3; d++) {
            atomicMin(&g_bmin[view][b][d], fenc(a[d]));
            atomicMax(&g_bmax[view][b][d], fenc(c[d]));
        }
    }
}

__global__ void finalize_bbox_kernel() {
    int t = blockIdx.x * 256 + threadIdx.x;  // 512
    int v = t >> 8, b = t & 255;
    for (int c = 0; c < 3; c++)
        g_bc[v][b][c] = (fdec(g_bmin[v][b][c]) + fdec(g_bmax[v][b][c])) * 0.5f;
}

__global__ void radius_kernel(const float* __restrict__ sel, int view) {
    int b = blockIdx.y;
    int j = blockIdx.x * 256 + threadIdx.x;
    float d2 = 0.0f;
    if (j < KK) {
        size_t o = ((size_t)b * KK + (unsigned)j) * 3;
        float dx = sel[o] - g_bc[view][b][0];
        float dy = sel[o + 1] - g_bc[view][b][1];
        float dz = sel[o + 2] - g_bc[view][b][2];
        d2 = dx * dx + dy * dy + dz * dz;
    }
#pragma unroll
    for (int off = 16; off; off >>= 1)
        d2 = fmaxf(d2, __shfl_xor_sync(0xFFFFFFFFu, d2, off));
    __shared__ float sm[8];
    int w = threadIdx.x >> 5, l = threadIdx.x & 31;
    if (l == 0) sm[w] = d2;
    __syncthreads();
    if (threadIdx.x == 0) {
        float m = sm[0];
        for (int ww = 1; ww < 8; ww++) m = fmaxf(m, sm[ww]);
        atomicMax(&g_rad[view][b], __float_as_uint(m));  // nonneg: bits monotone
    }
}

__global__ void finalize_r_kernel(float* __restrict__ out) {
    int t = blockIdx.x * 256 + threadIdx.x;  // 512
    int v = t >> 8, b = t & 255;
    float r = sqrtf(__uint_as_float(g_rad[v][b]));  // sqrt(max d2) == max(sqrt d2)
    g_invr[v][b] = 1.0f / r;
    float s, c;
    sincosf(g_theta[v][b], &s, &c);
    g_cs[v][b][0] = c; g_cs[v][b][1] = s;
    if (v == 0)
        for (int d = 0; d < 3; d++)
            out[b * 3 + d] = g_bc[1][b][d] - g_bc[0][b][d];  // relative_center = c2 - c1
}

__global__ void write_kernel(const float* __restrict__ sel, float* __restrict__ out,
                             int view) {
    int b = blockIdx.y;
    int j = blockIdx.x * 256 + threadIdx.x;
    if (j >= KK) return;
    size_t o = ((size_t)b * KK + (unsigned)j) * 3;
    float inv = g_invr[view][b];
    float px = (sel[o]     - g_bc[view][b][0]) * inv;
    float py = (sel[o + 1] - g_bc[view][b][1]) * inv;
    float pz = (sel[o + 2] - g_bc[view][b][2]) * inv;
    float c = g_cs[view][b][0], s = g_cs[view][b][1];
    float ox = px * c + py * s;   // einsum with R = [[c,-s,0],[s,c,0],[0,0,1]]
    float oy = py * c - px * s;
    size_t base = 768 + (size_t)view * ((size_t)BB * KK * 3);
    out[base + o]     = ox;
    out[base + o + 1] = oy;
    out[base + o + 2] = pz;
}

// ---------------- host ----------------
extern "C" void kernel_launch(void* const* d_in, const int* in_sizes, int n_in,
                              void* d_out, int out_size) {
    const float* pts = (const float*)d_in[0];
    const int* ci1 = (const int*)d_in[1];
    const int* ci2 = (const int*)d_in[2];
    float* out = (float*)d_out;

    unsigned *d2_1, *d2_2, *d2alt, *v1a, *v1b, *v2a, *v2b;
    void* tmp; float *sel1, *sel2;
    cudaGetSymbolAddress((void**)&d2_1, g_d2_1);
    cudaGetSymbolAddress((void**)&d2_2, g_d2_2);
    cudaGetSymbolAddress((void**)&d2alt, g_d2alt);
    cudaGetSymbolAddress((void**)&v1a, g_v1a);
    cudaGetSymbolAddress((void**)&v1b, g_v1b);
    cudaGetSymbolAddress((void**)&v2a, g_v2a);
    cudaGetSymbolAddress((void**)&v2b, g_v2b);
    cudaGetSymbolAddress(&tmp, g_temp);
    cudaGetSymbolAddress((void**)&sel1, g_sel1);
    cudaGetSymbolAddress((void**)&sel2, g_sel2);

    init_kernel<<<1, 256>>>(pts, ci1, ci2);
    keys_kernel<<<NTOT / 256, 256>>>(pts);

    size_t tb;

    // View 1: stable global pair-sort by d2 (32-bit key, 4 passes).
    // Input is batch-major + idx-ascending, so stable sort keeps per-batch
    // idx order on exact d2 ties (= confirmed lowest-index tie rule).
    cub::DoubleBuffer<unsigned> kd1(d2_1, d2alt);
    cub::DoubleBuffer<unsigned> vd1(v1a, v1b);
    tb = sizeof(g_temp);
    cub::DeviceRadixSort::SortPairs(tmp, tb, kd1, vd1, NTOT, 0, 32);

    // View 2 pair-sort (reuses key alternate buffer; keys are discarded after).
    cub::DoubleBuffer<unsigned> kd2(d2_2, d2alt);
    cub::DoubleBuffer<unsigned> vd2(v2a, v2b);
    tb = sizeof(g_temp);
    cub::DeviceRadixSort::SortPairs(tmp, tb, kd2, vd2, NTOT, 0, 32);

    // Batch split: ONE stable 8-bit pass on payload bits [16,24) (= batch id).
    // Restores batch-major layout while preserving d2-then-idx order per batch.
    cub::DoubleBuffer<unsigned> sp1(vd1.Current(), vd1.Alternate());
    tb = sizeof(g_temp);
    cub::DeviceRadixSort::SortKeys(tmp, tb, sp1, NTOT, 16, 24);
    const unsigned* s1 = sp1.Current();

    cub::DoubleBuffer<unsigned> sp2(vd2.Current(), vd2.Alternate());
    tb = sizeof(g_temp);
    cub::DeviceRadixSort::SortKeys(tmp, tb, sp2, NTOT, 16, 24);
    const unsigned* s2 = sp2.Current();

    dim3 grid((KK + 255) / 256, BB);
    gather_kernel<<<grid, 256>>>(s1, pts, sel1, 0);
    gather_kernel<<<grid, 256>>>(s2, pts, sel2, 1);
    finalize_bbox_kernel<<<2, 256>>>();
    radius_kernel<<<grid, 256>>>(sel1, 0);
    radius_kernel<<<grid, 256>>>(sel2, 1);
    finalize_r_kernel<<<2, 256>>>(out);
    write_kernel<<<grid, 256>>>(sel1, out, 0);
    write_kernel<<<grid, 256>>>(sel2, out, 1);
}

// round 15
// speedup vs baseline: 1.2237x; 1.0693x over previous
#include <cuda_runtime.h>
#include <cub/cub.cuh>
#include <stdint.h>

#define BB   256
#define NN   65536
#define KK   52428
#define NTOT (BB * NN)

// ---------------- static device scratch (no allocs allowed) ----------------
__device__ unsigned g_d2_1[NTOT];    // view1 d2 keys (input)
__device__ unsigned g_d2_2[NTOT];    // view2 d2 keys (input)
__device__ unsigned g_d2alt1[NTOT];  // view1 alternate key buffer
__device__ unsigned g_d2alt2[NTOT];  // view2 alternate key buffer
__device__ unsigned g_v1a[NTOT];     // view1 payload dbuf
__device__ unsigned g_v1b[NTOT];
__device__ unsigned g_v2a[NTOT];     // view2 payload dbuf
__device__ unsigned g_v2b[NTOT];
__device__ unsigned char g_temp1[48u * 1024u * 1024u];  // per-stream CUB temp
__device__ unsigned char g_temp2[48u * 1024u * 1024u];
__device__ float    g_sel1[(size_t)BB * KK * 3];
__device__ float    g_sel2[(size_t)BB * KK * 3];
__device__ float    g_cpt[2][BB][3];   // crop-center points
__device__ unsigned g_bmin[2][BB][3];  // encoded float atomics
__device__ unsigned g_bmax[2][BB][3];
__device__ unsigned g_rad[2][BB];      // max d^2 bits (nonneg float)
__device__ float    g_bc[2][BB][3];    // bbox centers
__device__ float    g_invr[2][BB];
__device__ float    g_cs[2][BB][2];    // cos, sin
__device__ float    g_theta[2][BB];

// ---------------- JAX threefry2x32 (exact) ----------------
__device__ __forceinline__ void tf2x32(unsigned k0, unsigned k1,
                                       unsigned c0, unsigned c1,
                                       unsigned& o0, unsigned& o1) {
    unsigned ks0 = k0, ks1 = k1, ks2 = k0 ^ k1 ^ 0x1BD11BDAu;
    unsigned x0 = c0 + ks0, x1 = c1 + ks1;
#define TF_RND(r) { x0 += x1; x1 = (x1 << (r)) | (x1 >> (32 - (r))); x1 ^= x0; }
    TF_RND(13) TF_RND(15) TF_RND(26) TF_RND(6)
    x0 += ks1; x1 += ks2 + 1u;
    TF_RND(17) TF_RND(29) TF_RND(16) TF_RND(24)
    x0 += ks2; x1 += ks0 + 2u;
    TF_RND(13) TF_RND(15) TF_RND(26) TF_RND(6)
    x0 += ks0; x1 += ks1 + 3u;
    TF_RND(17) TF_RND(29) TF_RND(16) TF_RND(24)
    x0 += ks1; x1 += ks2 + 4u;
    TF_RND(13) TF_RND(15) TF_RND(26) TF_RND(6)
    x0 += ks2; x1 += ks0 + 5u;
#undef TF_RND
    o0 = x0; o1 = x1;
}

__device__ __forceinline__ float bits_to_theta(unsigned u) {
    float f = __uint_as_float((u >> 9) | 0x3F800000u) - 1.0f;
    return fmaxf(0.0f, f * 6.2831855f);
}

// monotone float<->uint encodings for min/max atomics
__device__ __forceinline__ unsigned fenc(float f) {
    unsigned u = __float_as_uint(f);
    return (u & 0x80000000u) ? ~u : (u | 0x80000000u);
}
__device__ __forceinline__ float fdec(unsigned u) {
    return __uint_as_float((u & 0x80000000u) ? (u ^ 0x80000000u) : ~u);
}

// ---------------- kernels ----------------
__global__ void init_kernel(const float* __restrict__ pts,
                            const int* __restrict__ ci1,
                            const int* __restrict__ ci2) {
    int t = threadIdx.x;  // 256 threads, one block
    for (int v = 0; v < 2; v++) {
        for (int c = 0; c < 3; c++) { g_bmin[v][t][c] = 0xFFFFFFFFu; g_bmax[v][t][c] = 0u; }
        g_rad[v][t] = 0u;
    }
    int i1 = ci1[t], i2 = ci2[t];
    const float* p1 = pts + ((size_t)t * NN + (unsigned)i1) * 3;
    const float* p2 = pts + ((size_t)t * NN + (unsigned)i2) * 3;
    for (int c = 0; c < 3; c++) { g_cpt[0][t][c] = p1[c]; g_cpt[1][t][c] = p2[c]; }

    // JAX partitionable threefry (confirmed): split -> tf(key,(0,i)); bits = o0^o1
    unsigned k1a_, k1b_, k2a_, k2b_;
    tf2x32(0u, 42u, 0u, 0u, k1a_, k1b_);   // rk1
    tf2x32(0u, 42u, 0u, 1u, k2a_, k2b_);   // rk2
    unsigned o0, o1;
    tf2x32(k1a_, k1b_, 0u, (unsigned)t, o0, o1);
    g_theta[0][t] = bits_to_theta(o0 ^ o1);
    tf2x32(k2a_, k2b_, 0u, (unsigned)t, o0, o1);
    g_theta[1][t] = bits_to_theta(o0 ^ o1);
}

__global__ void keys_kernel(const float* __restrict__ pts) {
    int gid = blockIdx.x * 256 + threadIdx.x;
    int b = gid >> 16;
    size_t base = (size_t)gid * 3;
    float x = pts[base], y = pts[base + 1], z = pts[base + 2];
#pragma unroll
    for (int v = 0; v < 2; v++) {
        float dx = __fsub_rn(x, g_cpt[v][b][0]);
        float dy = __fsub_rn(y, g_cpt[v][b][1]);
        float dz = __fsub_rn(z, g_cpt[v][b][2]);
        float sx = __fmul_rn(dx, dx);
        float sy = __fmul_rn(dy, dy);
        float sz = __fmul_rn(dz, dz);
        // CONFIRMED formula F: (sx + sz) + sy — bit-exact vs reference.
        float d2 = __fadd_rn(__fadd_rn(sx, sz), sy);
        if (v == 0) g_d2_1[gid] = __float_as_uint(d2);
        else        g_d2_2[gid] = __float_as_uint(d2);
    }
    // Payload iota: gid == (batch<<16)|idx.
    g_v1a[gid] = (unsigned)gid;
    g_v2a[gid] = (unsigned)gid;
}

__global__ void gather_kernel(const unsigned* __restrict__ sorted,
                              const float* __restrict__ pts,
                              float* __restrict__ sel, int view) {
    int b = blockIdx.y;
    int j = blockIdx.x * 256 + threadIdx.x;
    const float INF = __int_as_float(0x7f800000);
    float mnx = INF, mny = INF, mnz = INF, mxx = -INF, mxy = -INF, mxz = -INF;
    if (j < KK) {
        unsigned idx = sorted[((size_t)b << 16) + (unsigned)j] & 0xFFFFu;
        const float* p = pts + (((size_t)b << 16) + idx) * 3;
        float x = p[0], y = p[1], z = p[2];
        size_t o = ((size_t)b * KK + (unsigned)j) * 3;
        sel[o] = x; sel[o + 1] = y; sel[o + 2] = z;
        mnx = mxx = x; mny = mxy = y; mnz = mxz = z;
    }
#pragma unroll
    for (int off = 16; off; off >>= 1) {
        mnx = fminf(mnx, __shfl_xor_sync(0xFFFFFFFFu, mnx, off));
        mny = fminf(mny, __shfl_xor_sync(0xFFFFFFFFu, mny, off));
        mnz = fminf(mnz, __shfl_xor_sync(0xFFFFFFFFu, mnz, off));
        mxx = fmaxf(mxx, __shfl_xor_sync(0xFFFFFFFFu, mxx, off));
        mxy = fmaxf(mxy, __shfl_xor_sync(0xFFFFFFFFu, mxy, off));
        mxz = fmaxf(mxz, __shfl_xor_sync(0xFFFFFFFFu, mxz, off));
    }
    __shared__ float smn[8][3], smx[8][3];
    int w = threadIdx.x >> 5, l = threadIdx.x & 31;
    if (l == 0) {
        smn[w][0] = mnx; smn[w][1] = mny; smn[w][2] = mnz;
        smx[w][0] = mxx; smx[w][1] = mxy; smx[w][2] = mxz;
    }
    __syncthreads();
    if (threadIdx.x == 0) {
        float a[3], c[3];
        for (int d = 0; d < 3; d++) { a[d] = smn[0][d]; c[d] = smx[0][d]; }
        for (int ww = 1; ww < 8; ww++)
            for (int d = 0; d < 3; d++) {
                a[d] = fminf(a[d], smn[ww][d]);
                c[d] = fmaxf(c[d], smx[ww][d]);
            }
        for (int d = 0; d < 3; d++) {
            atomicMin(&g_bmin[view][b][d], fenc(a[d]));
            atomicMax(&g_bmax[view][b][d], fenc(c[d]));
        }
    }
}

__global__ void finalize_bbox_kernel(int view) {
    int b = threadIdx.x;  // 256 threads, one block
    for (int c = 0; c < 3; c++)
        g_bc[view][b][c] = (fdec(g_bmin[view][b][c]) + fdec(g_bmax[view][b][c])) * 0.5f;
}

__global__ void radius_kernel(const float* __restrict__ sel, int view) {
    int b = blockIdx.y;
    int j = blockIdx.x * 256 + threadIdx.x;
    float d2 = 0.0f;
    if (j < KK) {
        size_t o = ((size_t)b * KK + (unsigned)j) * 3;
        float dx = sel[o] - g_bc[view][b][0];
        float dy = sel[o + 1] - g_bc[view][b][1];
        float dz = sel[o + 2] - g_bc[view][b][2];
        d2 = dx * dx + dy * dy + dz * dz;
    }
#pragma unroll
    for (int off = 16; off; off >>= 1)
        d2 = fmaxf(d2, __shfl_xor_sync(0xFFFFFFFFu, d2, off));
    __shared__ float sm[8];
    int w = threadIdx.x >> 5, l = threadIdx.x & 31;
    if (l == 0) sm[w] = d2;
    __syncthreads();
    if (threadIdx.x == 0) {
        float m = sm[0];
        for (int ww = 1; ww < 8; ww++) m = fmaxf(m, sm[ww]);
        atomicMax(&g_rad[view][b], __float_as_uint(m));  // nonneg: bits monotone
    }
}

__global__ void finalize_r_kernel(int view) {
    int b = threadIdx.x;  // 256 threads, one block
    float r = sqrtf(__uint_as_float(g_rad[view][b]));  // sqrt(max d2) == max(sqrt d2)
    g_invr[view][b] = 1.0f / r;
    float s, c;
    sincosf(g_theta[view][b], &s, &c);
    g_cs[view][b][0] = c; g_cs[view][b][1] = s;
}

__global__ void rc_kernel(float* __restrict__ out) {
    int b = threadIdx.x;  // 256 threads, one block; needs BOTH views' bc
    for (int d = 0; d < 3; d++)
        out[b * 3 + d] = g_bc[1][b][d] - g_bc[0][b][d];  // relative_center = c2 - c1
}

__global__ void write_kernel(const float* __restrict__ sel, float* __restrict__ out,
                             int view) {
    int b = blockIdx.y;
    int j = blockIdx.x * 256 + threadIdx.x;
    if (j >= KK) return;
    size_t o = ((size_t)b * KK + (unsigned)j) * 3;
    float inv = g_invr[view][b];
    float px = (sel[o]     - g_bc[view][b][0]) * inv;
    float py = (sel[o + 1] - g_bc[view][b][1]) * inv;
    float pz = (sel[o + 2] - g_bc[view][b][2]) * inv;
    float c = g_cs[view][b][0], s = g_cs[view][b][1];
    float ox = px * c + py * s;   // einsum with R = [[c,-s,0],[s,c,0],[0,0,1]]
    float oy = py * c - px * s;
    size_t base = 768 + (size_t)view * ((size_t)BB * KK * 3);
    out[base + o]     = ox;
    out[base + o + 1] = oy;
    out[base + o + 2] = pz;
}

// ---------------- host ----------------
extern "C" void kernel_launch(void* const* d_in, const int* in_sizes, int n_in,
                              void* d_out, int out_size) {
    const float* pts = (const float*)d_in[0];
    const int* ci1 = (const int*)d_in[1];
    const int* ci2 = (const int*)d_in[2];
    float* out = (float*)d_out;

    unsigned *d2_1, *d2_2, *alt1, *alt2, *v1a, *v1b, *v2a, *v2b;
    void *tmp1, *tmp2; float *sel1, *sel2;
    cudaGetSymbolAddress((void**)&d2_1, g_d2_1);
    cudaGetSymbolAddress((void**)&d2_2, g_d2_2);
    cudaGetSymbolAddress((void**)&alt1, g_d2alt1);
    cudaGetSymbolAddress((void**)&alt2, g_d2alt2);
    cudaGetSymbolAddress((void**)&v1a, g_v1a);
    cudaGetSymbolAddress((void**)&v1b, g_v1b);
    cudaGetSymbolAddress((void**)&v2a, g_v2a);
    cudaGetSymbolAddress((void**)&v2b, g_v2b);
    cudaGetSymbolAddress(&tmp1, g_temp1);
    cudaGetSymbolAddress(&tmp2, g_temp2);
    cudaGetSymbolAddress((void**)&sel1, g_sel1);
    cudaGetSymbolAddress((void**)&sel2, g_sel2);

    // Two concurrent per-view pipelines; fork/join via events so the captured
    // graph contains both branches in parallel (replay schedules them together).
    cudaStream_t s1, s2;
    cudaEvent_t e0, e1, e2;
    cudaStreamCreateWithFlags(&s1, cudaStreamNonBlocking);
    cudaStreamCreateWithFlags(&s2, cudaStreamNonBlocking);
    cudaEventCreateWithFlags(&e0, cudaEventDisableTiming);
    cudaEventCreateWithFlags(&e1, cudaEventDisableTiming);
    cudaEventCreateWithFlags(&e2, cudaEventDisableTiming);

    init_kernel<<<1, 256>>>(pts, ci1, ci2);
    keys_kernel<<<NTOT / 256, 256>>>(pts);
    cudaEventRecord(e0, 0);
    cudaStreamWaitEvent(s1, e0, 0);
    cudaStreamWaitEvent(s2, e0, 0);

    dim3 grid((KK + 255) / 256, BB);
    size_t tb;

    // ---- view 1 chain on s1 ----
    {
        cub::DoubleBuffer<unsigned> kd(d2_1, alt1);
        cub::DoubleBuffer<unsigned> vd(v1a, v1b);
        tb = sizeof(g_temp1);
        cub::DeviceRadixSort::SortPairs(tmp1, tb, kd, vd, NTOT, 0, 32, s1);
        cub::DoubleBuffer<unsigned> sp(vd.Current(), vd.Alternate());
        tb = sizeof(g_temp1);
        cub::DeviceRadixSort::SortKeys(tmp1, tb, sp, NTOT, 16, 24, s1);
        const unsigned* srt = sp.Current();
        gather_kernel<<<grid, 256, 0, s1>>>(srt, pts, sel1, 0);
        finalize_bbox_kernel<<<1, 256, 0, s1>>>(0);
        radius_kernel<<<grid, 256, 0, s1>>>(sel1, 0);
        finalize_r_kernel<<<1, 256, 0, s1>>>(0);
        write_kernel<<<grid, 256, 0, s1>>>(sel1, out, 0);
    }

    // ---- view 2 chain on s2 ----
    {
        cub::DoubleBuffer<unsigned> kd(d2_2, alt2);
        cub::DoubleBuffer<unsigned> vd(v2a, v2b);
        tb = sizeof(g_temp2);
        cub::DeviceRadixSort::SortPairs(tmp2, tb, kd, vd, NTOT, 0, 32, s2);
        cub::DoubleBuffer<unsigned> sp(vd.Current(), vd.Alternate());
        tb = sizeof(g_temp2);
        cub::DeviceRadixSort::SortKeys(tmp2, tb, sp, NTOT, 16, 24, s2);
        const unsigned* srt = sp.Current();
        gather_kernel<<<grid, 256, 0, s2>>>(srt, pts, sel2, 1);
        finalize_bbox_kernel<<<1, 256, 0, s2>>>(1);
        radius_kernel<<<grid, 256, 0, s2>>>(sel2, 1);
        finalize_r_kernel<<<1, 256, 0, s2>>>(1);
        write_kernel<<<grid, 256, 0, s2>>>(sel2, out, 1);
    }

    // ---- join; relative_center needs both views' bbox centers ----
    cudaEventRecord(e1, s1);
    cudaEventRecord(e2, s2);
    cudaStreamWaitEvent(0, e1, 0);
    cudaStreamWaitEvent(0, e2, 0);
    rc_kernel<<<1, 256>>>(out);

    cudaEventDestroy(e0);
    cudaEventDestroy(e1);
    cudaEventDestroy(e2);
    cudaStreamDestroy(s1);
    cudaStreamDestroy(s2);
}

// round 16
// speedup vs baseline: 1.3153x; 1.0748x over previous
#include <cuda_runtime.h>
#include <cub/cub.cuh>
#include <stdint.h>

#define BB   256
#define NN   65536
#define KK   52428
#define NTOT (BB * NN)

// ---------------- static device scratch (no allocs allowed) ----------------
__device__ unsigned g_d2_1[NTOT];     // view1 d2 keys (input)
__device__ unsigned g_d2_2[NTOT];     // view2 d2 keys (input)
__device__ unsigned g_d2alt1[NTOT];   // view1 alternate key buffer
__device__ unsigned g_d2alt2[NTOT];   // view2 alternate key buffer
__device__ unsigned short g_v1a[NTOT];  // view1 u16 idx payload dbuf
__device__ unsigned short g_v1b[NTOT];
__device__ unsigned short g_v2a[NTOT];  // view2 u16 idx payload dbuf
__device__ unsigned short g_v2b[NTOT];
__device__ int      g_offs[BB + 1];     // segment offsets i*NN
__device__ unsigned char g_temp1[48u * 1024u * 1024u];  // per-stream CUB temp
__device__ unsigned char g_temp2[48u * 1024u * 1024u];
__device__ float    g_sel1[(size_t)BB * KK * 3];
__device__ float    g_sel2[(size_t)BB * KK * 3];
__device__ float    g_cpt[2][BB][3];   // crop-center points
__device__ unsigned g_bmin[2][BB][3];  // encoded float atomics
__device__ unsigned g_bmax[2][BB][3];
__device__ unsigned g_rad[2][BB];      // max d^2 bits (nonneg float)
__device__ float    g_bc[2][BB][3];    // bbox centers
__device__ float    g_invr[2][BB];
__device__ float    g_cs[2][BB][2];    // cos, sin
__device__ float    g_theta[2][BB];

// ---------------- JAX threefry2x32 (exact) ----------------
__device__ __forceinline__ void tf2x32(unsigned k0, unsigned k1,
                                       unsigned c0, unsigned c1,
                                       unsigned& o0, unsigned& o1) {
    unsigned ks0 = k0, ks1 = k1, ks2 = k0 ^ k1 ^ 0x1BD11BDAu;
    unsigned x0 = c0 + ks0, x1 = c1 + ks1;
#define TF_RND(r) { x0 += x1; x1 = (x1 << (r)) | (x1 >> (32 - (r))); x1 ^= x0; }
    TF_RND(13) TF_RND(15) TF_RND(26) TF_RND(6)
    x0 += ks1; x1 += ks2 + 1u;
    TF_RND(17) TF_RND(29) TF_RND(16) TF_RND(24)
    x0 += ks2; x1 += ks0 + 2u;
    TF_RND(13) TF_RND(15) TF_RND(26) TF_RND(6)
    x0 += ks0; x1 += ks1 + 3u;
    TF_RND(17) TF_RND(29) TF_RND(16) TF_RND(24)
    x0 += ks1; x1 += ks2 + 4u;
    TF_RND(13) TF_RND(15) TF_RND(26) TF_RND(6)
    x0 += ks2; x1 += ks0 + 5u;
#undef TF_RND
    o0 = x0; o1 = x1;
}

__device__ __forceinline__ float bits_to_theta(unsigned u) {
    float f = __uint_as_float((u >> 9) | 0x3F800000u) - 1.0f;
    return fmaxf(0.0f, f * 6.2831855f);
}

// monotone float<->uint encodings for min/max atomics
__device__ __forceinline__ unsigned fenc(float f) {
    unsigned u = __float_as_uint(f);
    return (u & 0x80000000u) ? ~u : (u | 0x80000000u);
}
__device__ __forceinline__ float fdec(unsigned u) {
    return __uint_as_float((u & 0x80000000u) ? (u ^ 0x80000000u) : ~u);
}

// ---------------- kernels ----------------
__global__ void init_kernel(const float* __restrict__ pts,
                            const int* __restrict__ ci1,
                            const int* __restrict__ ci2) {
    int t = threadIdx.x;  // 256 threads, one block
    for (int v = 0; v < 2; v++) {
        for (int c = 0; c < 3; c++) { g_bmin[v][t][c] = 0xFFFFFFFFu; g_bmax[v][t][c] = 0u; }
        g_rad[v][t] = 0u;
    }
    g_offs[t] = t * NN;
    if (t == 0) g_offs[BB] = NTOT;
    int i1 = ci1[t], i2 = ci2[t];
    const float* p1 = pts + ((size_t)t * NN + (unsigned)i1) * 3;
    const float* p2 = pts + ((size_t)t * NN + (unsigned)i2) * 3;
    for (int c = 0; c < 3; c++) { g_cpt[0][t][c] = p1[c]; g_cpt[1][t][c] = p2[c]; }

    // JAX partitionable threefry (confirmed): split -> tf(key,(0,i)); bits = o0^o1
    unsigned k1a_, k1b_, k2a_, k2b_;
    tf2x32(0u, 42u, 0u, 0u, k1a_, k1b_);   // rk1
    tf2x32(0u, 42u, 0u, 1u, k2a_, k2b_);   // rk2
    unsigned o0, o1;
    tf2x32(k1a_, k1b_, 0u, (unsigned)t, o0, o1);
    g_theta[0][t] = bits_to_theta(o0 ^ o1);
    tf2x32(k2a_, k2b_, 0u, (unsigned)t, o0, o1);
    g_theta[1][t] = bits_to_theta(o0 ^ o1);
}

__global__ void keys_kernel(const float* __restrict__ pts) {
    int gid = blockIdx.x * 256 + threadIdx.x;
    int b = gid >> 16;
    size_t base = (size_t)gid * 3;
    float x = pts[base], y = pts[base + 1], z = pts[base + 2];
#pragma unroll
    for (int v = 0; v < 2; v++) {
        float dx = __fsub_rn(x, g_cpt[v][b][0]);
        float dy = __fsub_rn(y, g_cpt[v][b][1]);
        float dz = __fsub_rn(z, g_cpt[v][b][2]);
        float sx = __fmul_rn(dx, dx);
        float sy = __fmul_rn(dy, dy);
        float sz = __fmul_rn(dz, dz);
        // CONFIRMED formula F: (sx + sz) + sy — bit-exact vs reference.
        float d2 = __fadd_rn(__fadd_rn(sx, sz), sy);
        if (v == 0) g_d2_1[gid] = __float_as_uint(d2);
        else        g_d2_2[gid] = __float_as_uint(d2);
    }
    // Payload: local idx only; batch is implicit in the segment.
    unsigned short idx = (unsigned short)(gid & 0xFFFF);
    g_v1a[gid] = idx;
    g_v2a[gid] = idx;
}

__global__ void gather_kernel(const unsigned short* __restrict__ sorted,
                              const float* __restrict__ pts,
                              float* __restrict__ sel, int view) {
    int b = blockIdx.y;
    int j = blockIdx.x * 256 + threadIdx.x;
    const float INF = __int_as_float(0x7f800000);
    float mnx = INF, mny = INF, mnz = INF, mxx = -INF, mxy = -INF, mxz = -INF;
    if (j < KK) {
        unsigned idx = sorted[((size_t)b << 16) + (unsigned)j];
        const float* p = pts + (((size_t)b << 16) + idx) * 3;
        float x = p[0], y = p[1], z = p[2];
        size_t o = ((size_t)b * KK + (unsigned)j) * 3;
        sel[o] = x; sel[o + 1] = y; sel[o + 2] = z;
        mnx = mxx = x; mny = mxy = y; mnz = mxz = z;
    }
#pragma unroll
    for (int off = 16; off; off >>= 1) {
        mnx = fminf(mnx, __shfl_xor_sync(0xFFFFFFFFu, mnx, off));
        mny = fminf(mny, __shfl_xor_sync(0xFFFFFFFFu, mny, off));
        mnz = fminf(mnz, __shfl_xor_sync(0xFFFFFFFFu, mnz, off));
        mxx = fmaxf(mxx, __shfl_xor_sync(0xFFFFFFFFu, mxx, off));
        mxy = fmaxf(mxy, __shfl_xor_sync(0xFFFFFFFFu, mxy, off));
        mxz = fmaxf(mxz, __shfl_xor_sync(0xFFFFFFFFu, mxz, off));
    }
    __shared__ float smn[8][3], smx[8][3];
    int w = threadIdx.x >> 5, l = threadIdx.x & 31;
    if (l == 0) {
        smn[w][0] = mnx; smn[w][1] = mny; smn[w][2] = mnz;
        smx[w][0] = mxx; smx[w][1] = mxy; smx[w][2] = mxz;
    }
    __syncthreads();
    if (threadIdx.x == 0) {
        float a[3], c[3];
        for (int d = 0; d < 3; d++) { a[d] = smn[0][d]; c[d] = smx[0][d]; }
        for (int ww = 1; ww < 8; ww++)
            for (int d = 0; d < 3; d++) {
                a[d] = fminf(a[d], smn[ww][d]);
                c[d] = fmaxf(c[d], smx[ww][d]);
            }
        for (int d = 0; d < 3; d++) {
            atomicMin(&g_bmin[view][b][d], fenc(a[d]));
            atomicMax(&g_bmax[view][b][d], fenc(c[d]));
        }
    }
}

__global__ void finalize_bbox_kernel(int view) {
    int b = threadIdx.x;  // 256 threads, one block
    for (int c = 0; c < 3; c++)
        g_bc[view][b][c] = (fdec(g_bmin[view][b][c]) + fdec(g_bmax[view][b][c])) * 0.5f;
}

__global__ void radius_kernel(const float* __restrict__ sel, int view) {
    int b = blockIdx.y;
    int j = blockIdx.x * 256 + threadIdx.x;
    float d2 = 0.0f;
    if (j < KK) {
        size_t o = ((size_t)b * KK + (unsigned)j) * 3;
        float dx = sel[o] - g_bc[view][b][0];
        float dy = sel[o + 1] - g_bc[view][b][1];
        float dz = sel[o + 2] - g_bc[view][b][2];
        d2 = dx * dx + dy * dy + dz * dz;
    }
#pragma unroll
    for (int off = 16; off; off >>= 1)
        d2 = fmaxf(d2, __shfl_xor_sync(0xFFFFFFFFu, d2, off));
    __shared__ float sm[8];
    int w = threadIdx.x >> 5, l = threadIdx.x & 31;
    if (l == 0) sm[w] = d2;
    __syncthreads();
    if (threadIdx.x == 0) {
        float m = sm[0];
        for (int ww = 1; ww < 8; ww++) m = fmaxf(m, sm[ww]);
        atomicMax(&g_rad[view][b], __float_as_uint(m));  // nonneg: bits monotone
    }
}

__global__ void finalize_r_kernel(int view) {
    int b = threadIdx.x;  // 256 threads, one block
    float r = sqrtf(__uint_as_float(g_rad[view][b]));  // sqrt(max d2) == max(sqrt d2)
    g_invr[view][b] = 1.0f / r;
    float s, c;
    sincosf(g_theta[view][b], &s, &c);
    g_cs[view][b][0] = c; g_cs[view][b][1] = s;
}

__global__ void rc_kernel(float* __restrict__ out) {
    int b = threadIdx.x;  // 256 threads, one block; needs BOTH views' bc
    for (int d = 0; d < 3; d++)
        out[b * 3 + d] = g_bc[1][b][d] - g_bc[0][b][d];  // relative_center = c2 - c1
}

__global__ void write_kernel(const float* __restrict__ sel, float* __restrict__ out,
                             int view) {
    int b = blockIdx.y;
    int j = blockIdx.x * 256 + threadIdx.x;
    if (j >= KK) return;
    size_t o = ((size_t)b * KK + (unsigned)j) * 3;
    float inv = g_invr[view][b];
    float px = (sel[o]     - g_bc[view][b][0]) * inv;
    float py = (sel[o + 1] - g_bc[view][b][1]) * inv;
    float pz = (sel[o + 2] - g_bc[view][b][2]) * inv;
    float c = g_cs[view][b][0], s = g_cs[view][b][1];
    float ox = px * c + py * s;   // einsum with R = [[c,-s,0],[s,c,0],[0,0,1]]
    float oy = py * c - px * s;
    size_t base = 768 + (size_t)view * ((size_t)BB * KK * 3);
    out[base + o]     = ox;
    out[base + o + 1] = oy;
    out[base + o + 2] = pz;
}

// ---------------- host ----------------
extern "C" void kernel_launch(void* const* d_in, const int* in_sizes, int n_in,
                              void* d_out, int out_size) {
    const float* pts = (const float*)d_in[0];
    const int* ci1 = (const int*)d_in[1];
    const int* ci2 = (const int*)d_in[2];
    float* out = (float*)d_out;

    unsigned *d2_1, *d2_2, *alt1, *alt2;
    unsigned short *v1a, *v1b, *v2a, *v2b;
    int* offs;
    void *tmp1, *tmp2; float *sel1, *sel2;
    cudaGetSymbolAddress((void**)&d2_1, g_d2_1);
    cudaGetSymbolAddress((void**)&d2_2, g_d2_2);
    cudaGetSymbolAddress((void**)&alt1, g_d2alt1);
    cudaGetSymbolAddress((void**)&alt2, g_d2alt2);
    cudaGetSymbolAddress((void**)&v1a, g_v1a);
    cudaGetSymbolAddress((void**)&v1b, g_v1b);
    cudaGetSymbolAddress((void**)&v2a, g_v2a);
    cudaGetSymbolAddress((void**)&v2b, g_v2b);
    cudaGetSymbolAddress((void**)&offs, g_offs);
    cudaGetSymbolAddress(&tmp1, g_temp1);
    cudaGetSymbolAddress(&tmp2, g_temp2);
    cudaGetSymbolAddress((void**)&sel1, g_sel1);
    cudaGetSymbolAddress((void**)&sel2, g_sel2);

    cudaStream_t s1, s2;
    cudaEvent_t e0, e1, e2;
    cudaStreamCreateWithFlags(&s1, cudaStreamNonBlocking);
    cudaStreamCreateWithFlags(&s2, cudaStreamNonBlocking);
    cudaEventCreateWithFlags(&e0, cudaEventDisableTiming);
    cudaEventCreateWithFlags(&e1, cudaEventDisableTiming);
    cudaEventCreateWithFlags(&e2, cudaEventDisableTiming);

    init_kernel<<<1, 256>>>(pts, ci1, ci2);
    keys_kernel<<<NTOT / 256, 256>>>(pts);
    cudaEventRecord(e0, 0);
    cudaStreamWaitEvent(s1, e0, 0);
    cudaStreamWaitEvent(s2, e0, 0);

    dim3 grid((KK + 255) / 256, BB);
    size_t tb;

    // ---- view 1 chain on s1: segmented sort (256 segments of 64K) ----
    // Batch is implicit in the segment -> no batch-split pass, u16 payload.
    // Per-segment stable radix keeps the confirmed lowest-index tie rule.
    {
        cub::DoubleBuffer<unsigned> kd(d2_1, alt1);
        cub::DoubleBuffer<unsigned short> vd(v1a, v1b);
        tb = sizeof(g_temp1);
        cub::DeviceSegmentedRadixSort::SortPairs(tmp1, tb, kd, vd, NTOT, BB,
                                                 offs, offs + 1, 0, 32, s1);
        const unsigned short* srt = vd.Current();
        gather_kernel<<<grid, 256, 0, s1>>>(srt, pts, sel1, 0);
        finalize_bbox_kernel<<<1, 256, 0, s1>>>(0);
        radius_kernel<<<grid, 256, 0, s1>>>(sel1, 0);
        finalize_r_kernel<<<1, 256, 0, s1>>>(0);
        write_kernel<<<grid, 256, 0, s1>>>(sel1, out, 0);
    }

    // ---- view 2 chain on s2 ----
    {
        cub::DoubleBuffer<unsigned> kd(d2_2, alt2);
        cub::DoubleBuffer<unsigned short> vd(v2a, v2b);
        tb = sizeof(g_temp2);
        cub::DeviceSegmentedRadixSort::SortPairs(tmp2, tb, kd, vd, NTOT, BB,
                                                 offs, offs + 1, 0, 32, s2);
        const unsigned short* srt = vd.Current();
        gather_kernel<<<grid, 256, 0, s2>>>(srt, pts, sel2, 1);
        finalize_bbox_kernel<<<1, 256, 0, s2>>>(1);
        radius_kernel<<<grid, 256, 0, s2>>>(sel2, 1);
        finalize_r_kernel<<<1, 256, 0, s2>>>(1);
        write_kernel<<<grid, 256, 0, s2>>>(sel2, out, 1);
    }

    // ---- join; relative_center needs both views' bbox centers ----
    cudaEventRecord(e1, s1);
    cudaEventRecord(e2, s2);
    cudaStreamWaitEvent(0, e1, 0);
    cudaStreamWaitEvent(0, e2, 0);
    rc_kernel<<<1, 256>>>(out);

    cudaEventDestroy(e0);
    cudaEventDestroy(e1);
    cudaEventDestroy(e2);
    cudaStreamDestroy(s1);
    cudaStreamDestroy(s2);
}